// round 16
// baseline (speedup 1.0000x reference)
#include <cuda_runtime.h>
#include <cuda_fp16.h>
#include <cstdint>

#define NN 25000
#define EE 400000
#define NTILE 12500          // EE / 32 edges per warp-tile
#define GRID 444             // 3 CTAs / SM

__device__ int g_tick;       // dynamic tile ticket (reset inside k_node)

__device__ __forceinline__ uint32_t hmul2(uint32_t a, uint32_t b) {
    uint32_t r;
    asm("mul.rn.f16x2 %0, %1, %2;" : "=r"(r) : "r"(a), "r"(b));
    return r;
}
__device__ __forceinline__ uint32_t f2h2(float lo, float hi) {
    __half2 h = __floats2half2_rn(lo, hi);
    return *reinterpret_cast<uint32_t*>(&h);
}
__device__ __forceinline__ void mma16816(float* d,
                                         uint32_t a0, uint32_t a1,
                                         uint32_t a2, uint32_t a3,
                                         uint32_t b0, uint32_t b1) {
    asm volatile(
        "mma.sync.aligned.m16n8k16.row.col.f32.f16.f16.f32 "
        "{%0,%1,%2,%3}, {%4,%5,%6,%7}, {%8,%9}, {%0,%1,%2,%3};"
        : "+f"(d[0]), "+f"(d[1]), "+f"(d[2]), "+f"(d[3])
        : "r"(a0), "r"(a1), "r"(a2), "r"(a3), "r"(b0), "r"(b1));
}

// ---------------------------------------------------------------------------
// out = x @ node_W^T  (runs first; also resets the tile ticket for k_fused)
// ---------------------------------------------------------------------------
__global__ void k_node(const float* __restrict__ x,
                       const float* __restrict__ node_W,
                       float* __restrict__ out) {
    if (blockIdx.x == 0 && threadIdx.x == 0) g_tick = 0;
    __shared__ float nwT[32 * 33];
    const int t = threadIdx.x;
    for (int i = t; i < 1024; i += 256)
        nwT[(i & 31) * 33 + (i >> 5)] = node_W[i];   // nwT[d][h]
    __syncthreads();
    const int w = t >> 5, lane = t & 31;
    const int j = blockIdx.x * 8 + w;
    const float xr = x[j * 32 + lane];
    float acc = 0.f;
#pragma unroll
    for (int d = 0; d < 32; d++) {
        const float xd = __shfl_sync(0xffffffffu, xr, d);
        acc += xd * nwT[d * 33 + lane];
    }
    out[j * 32 + lane] = acc;
}

// ---------------------------------------------------------------------------
// Fused message+aggregate (warp = 32 edges x 32 cols x K=1024), dynamic
// ticket, shfl-shared splats (one shfl set per d-PAIR). No explicit B
// double-buffer: 24 warps/SM (3 CTAs) hide the LDS latency instead.
// ---------------------------------------------------------------------------
__global__ void __launch_bounds__(256, 3)
k_fused(const float* __restrict__ x, const float* __restrict__ ea,
        const float* __restrict__ eW, const int* __restrict__ ei,
        float* __restrict__ out) {
    extern __shared__ uint32_t Bf[];   // 16384 u32 = 64KB W2 fragments

    const int tid  = threadIdx.x;
    const int lane = tid & 31;
    const int g    = lane >> 2;        // mma group row 0..7
    const int tg   = lane & 3;         // thread-in-group

    // ---- stage B fragments: Bf[((d*2+k0i)*2+np)*128 + lane*4 + r] ----
    //  nt = np*2 + (r>>1), rr = r&1;  n = nt*8 + (ln>>2);
    //  k = k0i*16 + (ln&3)*2 + rr*8;  value = half2(W2[(d,k)][n], W2[(d,k+1)][n])
    //  with W2[(d,k)][h] = eW[d*1024 + h*32 + k]
    for (int i = tid; i < 16384; i += 256) {
        const int r   = i & 3;
        const int ln  = (i >> 2) & 31;
        const int np  = (i >> 7) & 1;
        const int k0i = (i >> 8) & 1;
        const int d   = i >> 9;
        const int nt  = np * 2 + (r >> 1);
        const int rr  = r & 1;
        const int n   = nt * 8 + (ln >> 2);
        const int k   = k0i * 16 + (ln & 3) * 2 + rr * 8;
        const float2 w = *reinterpret_cast<const float2*>(eW + d * 1024 + n * 32 + k);
        Bf[i] = f2h2(w.x, w.y);
    }
    __syncthreads();

    const uint4* B4 = reinterpret_cast<const uint4*>(Bf);

    for (;;) {
        int tile0 = 0;
        if (lane == 0) tile0 = atomicAdd(&g_tick, 1);
        const int tile = __shfl_sync(0xffffffffu, tile0, 0);
        if (tile >= NTILE) break;
        const int e0 = tile * 32;

        // x row for this lane's edge -> 16 half2 regs
        const int src = ei[e0 + lane];
        uint32_t xh[16];
        {
            const float4* xr = reinterpret_cast<const float4*>(x + (size_t)src * 32);
#pragma unroll
            for (int q = 0; q < 8; q++) {
                const float4 v = xr[q];
                xh[q * 2]     = f2h2(v.x, v.y);
                xh[q * 2 + 1] = f2h2(v.z, v.w);
            }
        }
        // ea fragments (register-resident): eaf[set][k0i][a0..a3]
        uint32_t eaf[2][2][4];
#pragma unroll
        for (int s = 0; s < 2; s++) {
            const float* r0 = ea + (size_t)(e0 + s * 16 + g) * 32;
            const float* r1 = r0 + 8 * 32;
#pragma unroll
            for (int k0i = 0; k0i < 2; k0i++) {
                const int c = k0i * 16 + tg * 2;
                float2 w;
                w = *reinterpret_cast<const float2*>(r0 + c);
                eaf[s][k0i][0] = f2h2(w.x, w.y);
                w = *reinterpret_cast<const float2*>(r1 + c);
                eaf[s][k0i][1] = f2h2(w.x, w.y);
                w = *reinterpret_cast<const float2*>(r0 + c + 8);
                eaf[s][k0i][2] = f2h2(w.x, w.y);
                w = *reinterpret_cast<const float2*>(r1 + c + 8);
                eaf[s][k0i][3] = f2h2(w.x, w.y);
            }
        }

        float dacc[8][4];   // [set*4 + nt][d0..d3]
#pragma unroll
        for (int q = 0; q < 8; q++)
#pragma unroll
            for (int i = 0; i < 4; i++) dacc[q][i] = 0.f;

        // -------- K loop: 16 d-pairs x 2 d x 2 k-chunks --------
#pragma unroll
        for (int dp = 0; dp < 16; dp++) {
            // one shfl set per d-pair (xv holds d=2dp and d=2dp+1)
            const uint32_t xv = xh[dp];
            const uint32_t r0 = __shfl_sync(0xffffffffu, xv, g);
            const uint32_t r1 = __shfl_sync(0xffffffffu, xv, g + 8);
            const uint32_t r2 = __shfl_sync(0xffffffffu, xv, g + 16);
            const uint32_t r3 = __shfl_sync(0xffffffffu, xv, g + 24);
#pragma unroll
            for (int dl = 0; dl < 2; dl++) {
                const uint32_t sel = dl ? 0x3232u : 0x1010u;
                const uint32_t s0 = __byte_perm(r0, 0u, sel);
                const uint32_t s1 = __byte_perm(r1, 0u, sel);
                const uint32_t s2 = __byte_perm(r2, 0u, sel);
                const uint32_t s3 = __byte_perm(r3, 0u, sel);
#pragma unroll
                for (int k0i = 0; k0i < 2; k0i++) {
                    const int idx = ((dp * 2 + dl) * 2 + k0i) * 2;
                    // both np halves issued back-to-back (MLP=2)
                    const uint4 b0 = B4[idx * 32 + lane];
                    const uint4 b1 = B4[(idx + 1) * 32 + lane];
                    uint32_t A[2][4];
                    A[0][0] = hmul2(s0, eaf[0][k0i][0]);
                    A[0][1] = hmul2(s1, eaf[0][k0i][1]);
                    A[0][2] = hmul2(s0, eaf[0][k0i][2]);
                    A[0][3] = hmul2(s1, eaf[0][k0i][3]);
                    A[1][0] = hmul2(s2, eaf[1][k0i][0]);
                    A[1][1] = hmul2(s3, eaf[1][k0i][1]);
                    A[1][2] = hmul2(s2, eaf[1][k0i][2]);
                    A[1][3] = hmul2(s3, eaf[1][k0i][3]);
#pragma unroll
                    for (int s = 0; s < 2; s++) {
                        mma16816(dacc[s * 4 + 0], A[s][0], A[s][1], A[s][2], A[s][3], b0.x, b0.y);
                        mma16816(dacc[s * 4 + 1], A[s][0], A[s][1], A[s][2], A[s][3], b0.z, b0.w);
                        mma16816(dacc[s * 4 + 2], A[s][0], A[s][1], A[s][2], A[s][3], b1.x, b1.y);
                        mma16816(dacc[s * 4 + 3], A[s][0], A[s][1], A[s][2], A[s][3], b1.z, b1.w);
                    }
                }
            }
        }

        // -------- epilogue: scatter-add D frags --------
#pragma unroll
        for (int s = 0; s < 2; s++) {
            const int dst0 = ei[EE + e0 + s * 16 + g];
            const int dst1 = ei[EE + e0 + s * 16 + g + 8];
#pragma unroll
            for (int nt = 0; nt < 4; nt++) {
                float* p0 = out + (size_t)dst0 * 32 + nt * 8 + tg * 2;
                float* p1 = out + (size_t)dst1 * 32 + nt * 8 + tg * 2;
                asm volatile("red.global.add.v2.f32 [%0], {%1,%2};"
                             :: "l"(p0), "f"(dacc[s * 4 + nt][0]),
                                "f"(dacc[s * 4 + nt][1]) : "memory");
                asm volatile("red.global.add.v2.f32 [%0], {%1,%2};"
                             :: "l"(p1), "f"(dacc[s * 4 + nt][2]),
                                "f"(dacc[s * 4 + nt][3]) : "memory");
            }
        }
    }
}

// ---------------------------------------------------------------------------
extern "C" void kernel_launch(void* const* d_in, const int* in_sizes, int n_in,
                              void* d_out, int out_size) {
    const float* x          = (const float*)d_in[0];  // [25000,32]
    const float* edge_attr  = (const float*)d_in[1];  // [400000,32]
    const float* edge_W     = (const float*)d_in[2];  // [1024,32]
    const float* node_W     = (const float*)d_in[3];  // [32,32]
    const int*   edge_index = (const int*)d_in[4];    // [2,400000]
    float* out = (float*)d_out;

    const int smem = 16384 * 4;   // 64KB B fragments
    cudaFuncSetAttribute(k_fused, cudaFuncAttributeMaxDynamicSharedMemorySize,
                         smem);

    k_node<<<NN / 8, 256>>>(x, node_W, out);   // also resets g_tick
    k_fused<<<GRID, 256, smem>>>(x, edge_attr, edge_W, edge_index, out);
}

// round 17
// speedup vs baseline: 1.1942x; 1.1942x over previous
#include <cuda_runtime.h>
#include <cuda_fp16.h>
#include <cstdint>

#define NN 25000
#define EE 400000
#define NTILE 12500          // EE / 32 edges per warp-tile
#define GRID 296             // 2 CTAs / SM

__device__ int g_tick;       // dynamic tile ticket (reset inside k_node)

__device__ __forceinline__ uint32_t hmul2(uint32_t a, uint32_t b) {
    uint32_t r;
    asm("mul.rn.f16x2 %0, %1, %2;" : "=r"(r) : "r"(a), "r"(b));
    return r;
}
__device__ __forceinline__ uint32_t f2h2(float lo, float hi) {
    __half2 h = __floats2half2_rn(lo, hi);
    return *reinterpret_cast<uint32_t*>(&h);
}
__device__ __forceinline__ void mma16816(float* d,
                                         uint32_t a0, uint32_t a1,
                                         uint32_t a2, uint32_t a3,
                                         uint32_t b0, uint32_t b1) {
    asm volatile(
        "mma.sync.aligned.m16n8k16.row.col.f32.f16.f16.f32 "
        "{%0,%1,%2,%3}, {%4,%5,%6,%7}, {%8,%9}, {%0,%1,%2,%3};"
        : "+f"(d[0]), "+f"(d[1]), "+f"(d[2]), "+f"(d[3])
        : "r"(a0), "r"(a1), "r"(a2), "r"(a3), "r"(b0), "r"(b1));
}

// ---------------------------------------------------------------------------
// out = x @ node_W^T  (runs first; also resets the tile ticket for k_fused)
// ---------------------------------------------------------------------------
__global__ void k_node(const float* __restrict__ x,
                       const float* __restrict__ node_W,
                       float* __restrict__ out) {
    if (blockIdx.x == 0 && threadIdx.x == 0) g_tick = 0;
    __shared__ float nwT[32 * 33];
    const int t = threadIdx.x;
    for (int i = t; i < 1024; i += 256)
        nwT[(i & 31) * 33 + (i >> 5)] = node_W[i];   // nwT[d][h]
    __syncthreads();
    const int w = t >> 5, lane = t & 31;
    const int j = blockIdx.x * 8 + w;
    const float xr = x[j * 32 + lane];
    float acc = 0.f;
#pragma unroll
    for (int d = 0; d < 32; d++) {
        const float xd = __shfl_sync(0xffffffffu, xr, d);
        acc += xd * nwT[d * 33 + lane];
    }
    out[j * 32 + lane] = acc;
}

// ---------------------------------------------------------------------------
// Fused message+aggregate (R15 k_fused + dst-load hoist): warp = 32 edges x
// 32 cols x K=1024, B double-buffer prefetch, dynamic tile ticket. The dst
// indices are loaded in the tile prologue so the K-loop hides their latency.
// ---------------------------------------------------------------------------
__global__ void __launch_bounds__(256, 2)
k_fused(const float* __restrict__ x, const float* __restrict__ ea,
        const float* __restrict__ eW, const int* __restrict__ ei,
        float* __restrict__ out) {
    extern __shared__ uint32_t Bf[];   // 16384 u32 W2 frags + 128 u32 pad

    const int tid  = threadIdx.x;
    const int lane = tid & 31;
    const int g    = lane >> 2;        // mma group row 0..7
    const int tg   = lane & 3;         // thread-in-group

    // ---- stage B fragments: Bf[((d*2+k0i)*2+np)*128 + lane*4 + r] ----
    //  nt = np*2 + (r>>1), rr = r&1;  n = nt*8 + (ln>>2);
    //  k = k0i*16 + (ln&3)*2 + rr*8;  value = half2(W2[(d,k)][n], W2[(d,k+1)][n])
    //  with W2[(d,k)][h] = eW[d*1024 + h*32 + k]
    for (int i = tid; i < 16384; i += 256) {
        const int r   = i & 3;
        const int ln  = (i >> 2) & 31;
        const int np  = (i >> 7) & 1;
        const int k0i = (i >> 8) & 1;
        const int d   = i >> 9;
        const int nt  = np * 2 + (r >> 1);
        const int rr  = r & 1;
        const int n   = nt * 8 + (ln >> 2);
        const int k   = k0i * 16 + (ln & 3) * 2 + rr * 8;
        const float2 w = *reinterpret_cast<const float2*>(eW + d * 1024 + n * 32 + k);
        Bf[i] = f2h2(w.x, w.y);
    }
    // zero the prefetch-overrun pad (idx 128 reads land here)
    for (int i = tid; i < 128; i += 256) Bf[16384 + i] = 0;
    __syncthreads();

    const uint4* B4 = reinterpret_cast<const uint4*>(Bf);

    for (;;) {
        int tile0 = 0;
        if (lane == 0) tile0 = atomicAdd(&g_tick, 1);
        const int tile = __shfl_sync(0xffffffffu, tile0, 0);
        if (tile >= NTILE) break;
        const int e0 = tile * 32;

        // src + dst indices up front (dst latency hidden by the K-loop)
        const int src  = ei[e0 + lane];
        const int dst0 = ei[EE + e0 + g];
        const int dst1 = ei[EE + e0 + g + 8];
        const int dst2 = ei[EE + e0 + 16 + g];
        const int dst3 = ei[EE + e0 + 24 + g];

        // x row for this lane's edge -> 16 half2 regs
        uint32_t xh[16];
        {
            const float4* xr = reinterpret_cast<const float4*>(x + (size_t)src * 32);
#pragma unroll
            for (int q = 0; q < 8; q++) {
                const float4 v = xr[q];
                xh[q * 2]     = f2h2(v.x, v.y);
                xh[q * 2 + 1] = f2h2(v.z, v.w);
            }
        }
        // ea fragments (register-resident): eaf[set][k0i][a0..a3]
        uint32_t eaf[2][2][4];
#pragma unroll
        for (int s = 0; s < 2; s++) {
            const float* r0 = ea + (size_t)(e0 + s * 16 + g) * 32;
            const float* r1 = r0 + 8 * 32;
#pragma unroll
            for (int k0i = 0; k0i < 2; k0i++) {
                const int c = k0i * 16 + tg * 2;
                float2 w;
                w = *reinterpret_cast<const float2*>(r0 + c);
                eaf[s][k0i][0] = f2h2(w.x, w.y);
                w = *reinterpret_cast<const float2*>(r1 + c);
                eaf[s][k0i][1] = f2h2(w.x, w.y);
                w = *reinterpret_cast<const float2*>(r0 + c + 8);
                eaf[s][k0i][2] = f2h2(w.x, w.y);
                w = *reinterpret_cast<const float2*>(r1 + c + 8);
                eaf[s][k0i][3] = f2h2(w.x, w.y);
            }
        }

        float dacc[8][4];   // [set*4 + nt][d0..d3]
#pragma unroll
        for (int q = 0; q < 8; q++)
#pragma unroll
            for (int i = 0; i < 4; i++) dacc[q][i] = 0.f;

        // -------- K loop with B double-buffer prefetch --------
        uint4 b = B4[lane];                    // idx 0 (d=0,k0i=0,np=0)
#pragma unroll
        for (int d = 0; d < 32; d++) {
            const uint32_t xv  = xh[d >> 1];
            const uint32_t sel = (d & 1) ? 0x3232u : 0x1010u;
            const uint32_t s0 = __byte_perm(__shfl_sync(0xffffffffu, xv, g),      0u, sel);
            const uint32_t s1 = __byte_perm(__shfl_sync(0xffffffffu, xv, g + 8),  0u, sel);
            const uint32_t s2 = __byte_perm(__shfl_sync(0xffffffffu, xv, g + 16), 0u, sel);
            const uint32_t s3 = __byte_perm(__shfl_sync(0xffffffffu, xv, g + 24), 0u, sel);
#pragma unroll
            for (int k0i = 0; k0i < 2; k0i++) {
                const int idx = (d * 2 + k0i) * 2;        // np=0 slot
                uint32_t A[2][4];
                A[0][0] = hmul2(s0, eaf[0][k0i][0]);
                A[0][1] = hmul2(s1, eaf[0][k0i][1]);
                A[0][2] = hmul2(s0, eaf[0][k0i][2]);
                A[0][3] = hmul2(s1, eaf[0][k0i][3]);
                A[1][0] = hmul2(s2, eaf[1][k0i][0]);
                A[1][1] = hmul2(s3, eaf[1][k0i][1]);
                A[1][2] = hmul2(s2, eaf[1][k0i][2]);
                A[1][3] = hmul2(s3, eaf[1][k0i][3]);

                // prefetch np=1 before consuming np=0
                const uint4 b1 = B4[(idx + 1) * 32 + lane];
#pragma unroll
                for (int s = 0; s < 2; s++) {
                    mma16816(dacc[s * 4 + 0], A[s][0], A[s][1], A[s][2], A[s][3], b.x, b.y);
                    mma16816(dacc[s * 4 + 1], A[s][0], A[s][1], A[s][2], A[s][3], b.z, b.w);
                }
                // prefetch next (d,k0i) np=0 (idx+2; pad absorbs overrun)
                const uint4 b0n = B4[(idx + 2) * 32 + lane];
#pragma unroll
                for (int s = 0; s < 2; s++) {
                    mma16816(dacc[s * 4 + 2], A[s][0], A[s][1], A[s][2], A[s][3], b1.x, b1.y);
                    mma16816(dacc[s * 4 + 3], A[s][0], A[s][1], A[s][2], A[s][3], b1.z, b1.w);
                }
                b = b0n;
            }
        }

        // -------- epilogue: scatter-add D frags (dst already resident) ----
        const int dsts[4] = {dst0, dst1, dst2, dst3};
#pragma unroll
        for (int s = 0; s < 2; s++) {
#pragma unroll
            for (int nt = 0; nt < 4; nt++) {
                float* p0 = out + (size_t)dsts[s * 2]     * 32 + nt * 8 + tg * 2;
                float* p1 = out + (size_t)dsts[s * 2 + 1] * 32 + nt * 8 + tg * 2;
                asm volatile("red.global.add.v2.f32 [%0], {%1,%2};"
                             :: "l"(p0), "f"(dacc[s * 4 + nt][0]),
                                "f"(dacc[s * 4 + nt][1]) : "memory");
                asm volatile("red.global.add.v2.f32 [%0], {%1,%2};"
                             :: "l"(p1), "f"(dacc[s * 4 + nt][2]),
                                "f"(dacc[s * 4 + nt][3]) : "memory");
            }
        }
    }
}

// ---------------------------------------------------------------------------
extern "C" void kernel_launch(void* const* d_in, const int* in_sizes, int n_in,
                              void* d_out, int out_size) {
    const float* x          = (const float*)d_in[0];  // [25000,32]
    const float* edge_attr  = (const float*)d_in[1];  // [400000,32]
    const float* edge_W     = (const float*)d_in[2];  // [1024,32]
    const float* node_W     = (const float*)d_in[3];  // [32,32]
    const int*   edge_index = (const int*)d_in[4];    // [2,400000]
    float* out = (float*)d_out;

    const int smem = (16384 + 128) * 4;   // 64KB B frags + prefetch pad
    cudaFuncSetAttribute(k_fused, cudaFuncAttributeMaxDynamicSharedMemorySize,
                         smem);

    k_node<<<NN / 8, 256>>>(x, node_W, out);   // also resets g_tick
    k_fused<<<GRID, 256, smem>>>(x, edge_attr, edge_W, edge_index, out);
}